// round 2
// baseline (speedup 1.0000x reference)
#include <cuda_runtime.h>
#include <math.h>

#define NMAX 50000
#define EMAX 1600000
#define D 128
#define T 16
#define RP 20   // padded smem row stride (floats): 4-way write conflicts, 16B-aligned float4 reads

// ---- scratch (static device globals; no allocation anywhere) ----
__device__ float g_buf[2][2][NMAX * D];      // [graph][ping-pong][N*D]
__device__ int   g_deg[2][NMAX];
__device__ int   g_rowstart[2][NMAX + 1];
__device__ int   g_cursor[2][NMAX];
__device__ int   g_csr[2][EMAX];
__device__ float g_invdeg[2][NMAX];
__device__ float g_colsum[2 * D];

// ---------------- init: zero degrees (both graphs) + colsum ----------------
__global__ void k_init(int n) {
    int gi = blockIdx.y;
    int i = blockIdx.x * blockDim.x + threadIdx.x;
    if (i < n) g_deg[gi][i] = 0;
    if (gi == 0 && blockIdx.x == 0 && threadIdx.x < 2 * D) g_colsum[threadIdx.x] = 0.f;
}

// ---------------- degree count (both graphs) ----------------
__global__ void k_count(const int* __restrict__ d0, const int* __restrict__ d1,
                        int e0, int e1) {
    int gi = blockIdx.y;
    const int* __restrict__ dst = gi ? d1 : d0;
    int e = gi ? e1 : e0;
    int i = blockIdx.x * blockDim.x + threadIdx.x;
    if (i < e) atomicAdd(&g_deg[gi][dst[i]], 1);
}

// ---------------- fast exclusive scan: 1 block per graph, warp shuffles ----------------
__global__ void k_scan(int n) {
    int gi = blockIdx.x;
    const int* __restrict__ deg = g_deg[gi];
    int* __restrict__ rowstart = g_rowstart[gi];
    int* __restrict__ cursor = g_cursor[gi];
    float* __restrict__ invdeg = g_invdeg[gi];

    __shared__ int s_warp[32];
    __shared__ int s_carry;
    int tid = threadIdx.x;
    int lane = tid & 31;
    int wid = tid >> 5;
    if (tid == 0) s_carry = 0;
    __syncthreads();

    for (int base = 0; base < n; base += 1024) {
        int i = base + tid;
        int v = (i < n) ? deg[i] : 0;
        // inclusive warp scan
        int s = v;
        #pragma unroll
        for (int d = 1; d < 32; d <<= 1) {
            int t = __shfl_up_sync(0xffffffffu, s, d);
            if (lane >= d) s += t;
        }
        if (lane == 31) s_warp[wid] = s;
        __syncthreads();
        if (wid == 0) {
            int w = s_warp[lane];
            #pragma unroll
            for (int d = 1; d < 32; d <<= 1) {
                int t = __shfl_up_sync(0xffffffffu, w, d);
                if (lane >= d) w += t;
            }
            s_warp[lane] = w;   // inclusive warp sums
        }
        __syncthreads();
        int carry = s_carry;
        int excl = carry + (wid ? s_warp[wid - 1] : 0) + s - v;
        if (i < n) {
            rowstart[i] = excl;
            cursor[i]   = excl;
            invdeg[i]   = 1.0f / fmaxf((float)v, 1.0f);
        }
        __syncthreads();   // everyone has read s_carry / s_warp
        if (tid == 0) s_carry = carry + s_warp[31];
        __syncthreads();
    }
    if (tid == 0) rowstart[n] = s_carry;
}

// ---------------- CSR fill (both graphs) ----------------
__global__ void k_fill(const int* __restrict__ s0, const int* __restrict__ d0,
                       const int* __restrict__ s1, const int* __restrict__ d1,
                       int e0, int e1) {
    int gi = blockIdx.y;
    const int* __restrict__ src = gi ? s1 : s0;
    const int* __restrict__ dst = gi ? d1 : d0;
    int e = gi ? e1 : e0;
    int i = blockIdx.x * blockDim.x + threadIdx.x;
    if (i < e) {
        int p = atomicAdd(&g_cursor[gi][dst[i]], 1);
        g_csr[gi][p] = src[i];
    }
}

// ---------------- fused aggregate (mean over in-edges) + GEMM + bias ----------------
// block = 128 threads (one per feature), T=16 nodes, both graphs via blockIdx.y
__global__ void __launch_bounds__(128) k_layer(
    const float* __restrict__ fp, const float* __restrict__ fs,
    int sel_in, int sel_out,
    const float* __restrict__ W, const float* __restrict__ bias, int n)
{
    int gi = blockIdx.y;
    const float* __restrict__ h_in =
        (sel_in < 0) ? (gi ? fs : fp) : g_buf[gi][sel_in];
    float* __restrict__ h_out = g_buf[gi][sel_out];
    const int* __restrict__ rowstart = g_rowstart[gi];
    const int* __restrict__ csr = g_csr[gi];
    const float* __restrict__ invdeg = g_invdeg[gi];

    __shared__ float rows[D][RP];   // [k][t] padded
    int tid  = threadIdx.x;
    int base = blockIdx.x * T;

    // aggregation: thread tid accumulates feature column tid for each of T nodes
    #pragma unroll
    for (int t = 0; t < T; t++) {
        int node = base + t;
        float acc = 0.f;
        if (node < n) {
            int s = rowstart[node];
            int e = rowstart[node + 1];
            float a0 = 0.f, a1 = 0.f, a2 = 0.f, a3 = 0.f;
            int i = s;
            for (; i + 4 <= e; i += 4) {
                int c0 = csr[i], c1 = csr[i + 1], c2 = csr[i + 2], c3 = csr[i + 3];
                a0 += h_in[(size_t)c0 * D + tid];
                a1 += h_in[(size_t)c1 * D + tid];
                a2 += h_in[(size_t)c2 * D + tid];
                a3 += h_in[(size_t)c3 * D + tid];
            }
            for (; i < e; i++) a0 += h_in[(size_t)csr[i] * D + tid];
            acc = ((a0 + a1) + (a2 + a3)) * invdeg[node];
        }
        rows[tid][t] = acc;
    }
    __syncthreads();

    // GEMM: out[node][tid] = sum_k rows[k][node] * W[k][tid] + b[tid]
    float accv[T];
    float bv = bias[tid];
    #pragma unroll
    for (int t = 0; t < T; t++) accv[t] = bv;

    #pragma unroll 2
    for (int k = 0; k < D; k++) {
        float w = W[k * D + tid];
        float4 r0 = *(const float4*)&rows[k][0];
        float4 r1 = *(const float4*)&rows[k][4];
        float4 r2 = *(const float4*)&rows[k][8];
        float4 r3 = *(const float4*)&rows[k][12];
        accv[0]  += r0.x * w; accv[1]  += r0.y * w;
        accv[2]  += r0.z * w; accv[3]  += r0.w * w;
        accv[4]  += r1.x * w; accv[5]  += r1.y * w;
        accv[6]  += r1.z * w; accv[7]  += r1.w * w;
        accv[8]  += r2.x * w; accv[9]  += r2.y * w;
        accv[10] += r2.z * w; accv[11] += r2.w * w;
        accv[12] += r3.x * w; accv[13] += r3.y * w;
        accv[14] += r3.z * w; accv[15] += r3.w * w;
    }

    #pragma unroll
    for (int t = 0; t < T; t++) {
        int node = base + t;
        if (node < n) h_out[(size_t)node * D + tid] = accv[t];
    }
}

// ---------------- readout column sums over final h (both graphs) ----------------
__global__ void k_colsum(int n) {
    int gi = blockIdx.y;
    float acc = 0.f;
    for (int node = blockIdx.x; node < n; node += gridDim.x)
        acc += g_buf[gi][0][(size_t)node * D + threadIdx.x];
    atomicAdd(&g_colsum[gi * D + threadIdx.x], acc);
}

// ---------------- final: readout MLP + match MLP + sigmoid ----------------
__global__ void k_match(const float* __restrict__ Wr,  const float* __restrict__ br,
                        const float* __restrict__ Wm1, const float* __restrict__ bm1,
                        const float* __restrict__ Wm2, const float* __restrict__ bm2,
                        float n_nodes, float* __restrict__ out)
{
    __shared__ float c[2 * D];
    __shared__ float red[D];
    int tid = threadIdx.x;          // 256 threads
    int g = tid / D;
    int j = tid % D;
    float invn = 1.0f / n_nodes;

    float acc = br[j];
    for (int k = 0; k < D; k++)
        acc += (g_colsum[g * D + k] * invn) * Wr[k * D + j];
    c[tid] = 1.0f / (1.0f + expf(-acc));    // g_p / g_s concatenated
    __syncthreads();

    if (tid < D) {
        float d1 = bm1[tid];
        for (int i = 0; i < 2 * D; i++)
            d1 += c[i] * Wm1[i * D + tid];
        red[tid] = d1 * Wm2[tid];
    }
    __syncthreads();

    if (tid == 0) {
        float s = 0.f;
        for (int i = 0; i < D; i++) s += red[i];
        out[0] = 1.0f / (1.0f + expf(-(s + bm2[0])));
    }
}

// ---------------- launch ----------------
extern "C" void kernel_launch(void* const* d_in, const int* in_sizes, int n_in,
                              void* d_out, int out_size)
{
    const float* feat_p = (const float*)d_in[0];
    const int*   src_p  = (const int*)d_in[1];
    const int*   dst_p  = (const int*)d_in[2];
    const float* feat_s = (const float*)d_in[3];
    const int*   src_s  = (const int*)d_in[4];
    const int*   dst_s  = (const int*)d_in[5];
    const float* W[3]   = { (const float*)d_in[6], (const float*)d_in[8], (const float*)d_in[10] };
    const float* b[3]   = { (const float*)d_in[7], (const float*)d_in[9], (const float*)d_in[11] };
    const float* Wr  = (const float*)d_in[12];
    const float* br  = (const float*)d_in[13];
    const float* Wm1 = (const float*)d_in[14];
    const float* bm1 = (const float*)d_in[15];
    const float* Wm2 = (const float*)d_in[16];
    const float* bm2 = (const float*)d_in[17];

    int n  = in_sizes[0] / D;
    int e0 = in_sizes[1];
    int e1 = in_sizes[4];
    int emax = e0 > e1 ? e0 : e1;

    dim3 gN((n + 511) / 512, 2);
    dim3 gE((emax + 511) / 512, 2);

    k_init<<<gN, 512>>>(n);
    k_count<<<gE, 512>>>(dst_p, dst_s, e0, e1);
    k_scan<<<2, 1024>>>(n);
    k_fill<<<gE, 512>>>(src_p, dst_p, src_s, dst_s, e0, e1);

    dim3 gL((n + T - 1) / T, 2);
    k_layer<<<gL, 128>>>(feat_p, feat_s, -1, 0, W[0], b[0], n);  // feat -> A
    k_layer<<<gL, 128>>>(feat_p, feat_s,  0, 1, W[1], b[1], n);  // A -> B
    k_layer<<<gL, 128>>>(feat_p, feat_s,  1, 0, W[2], b[2], n);  // B -> A

    dim3 gC(512, 2);
    k_colsum<<<gC, 128>>>(n);

    k_match<<<1, 256>>>(Wr, br, Wm1, bm1, Wm2, bm2, (float)n, (float*)d_out);
}

// round 3
// speedup vs baseline: 1.1397x; 1.1397x over previous
#include <cuda_runtime.h>
#include <math.h>

#define NMAX 50000
#define EMAX 1600000
#define D 128
#define T 8
#define RP 10   // padded smem row stride (floats): 8B-aligned, 2-way write conflicts

// ---- scratch (static device globals; no allocation anywhere) ----
__device__ float g_buf[2][2][NMAX * D];      // [graph][ping-pong][N*D]
__device__ int   g_deg[2][NMAX];
__device__ int   g_rowstart[2][NMAX + 1];
__device__ int   g_cursor[2][NMAX];
__device__ int   g_csr[2][EMAX];
__device__ float g_invdeg[2][NMAX];
__device__ float g_colsum[2 * D];

// ---- f32x2 packed helpers ----
__device__ __forceinline__ unsigned long long pack2(float lo, float hi) {
    unsigned long long r;
    asm("mov.b64 %0, {%1, %2};" : "=l"(r) : "f"(lo), "f"(hi));
    return r;
}
__device__ __forceinline__ void unpack2(unsigned long long v, float& lo, float& hi) {
    asm("mov.b64 {%0, %1}, %2;" : "=f"(lo), "=f"(hi) : "l"(v));
}
__device__ __forceinline__ unsigned long long fma2(unsigned long long a,
                                                   unsigned long long b,
                                                   unsigned long long c) {
    unsigned long long d;
    asm("fma.rn.f32x2 %0, %1, %2, %3;" : "=l"(d) : "l"(a), "l"(b), "l"(c));
    return d;
}

// ---------------- init: zero degrees (both graphs) + colsum ----------------
__global__ void k_init(int n) {
    int gi = blockIdx.y;
    int i = blockIdx.x * blockDim.x + threadIdx.x;
    if (i < n) g_deg[gi][i] = 0;
    if (gi == 0 && blockIdx.x == 0 && threadIdx.x < 2 * D) g_colsum[threadIdx.x] = 0.f;
}

// ---------------- degree count (both graphs) ----------------
__global__ void k_count(const int* __restrict__ d0, const int* __restrict__ d1,
                        int e0, int e1) {
    int gi = blockIdx.y;
    const int* __restrict__ dst = gi ? d1 : d0;
    int e = gi ? e1 : e0;
    int i = blockIdx.x * blockDim.x + threadIdx.x;
    if (i < e) atomicAdd(&g_deg[gi][dst[i]], 1);
}

// ---------------- fast exclusive scan: 1 block per graph, warp shuffles ----------------
__global__ void k_scan(int n) {
    int gi = blockIdx.x;
    const int* __restrict__ deg = g_deg[gi];
    int* __restrict__ rowstart = g_rowstart[gi];
    int* __restrict__ cursor = g_cursor[gi];
    float* __restrict__ invdeg = g_invdeg[gi];

    __shared__ int s_warp[32];
    __shared__ int s_carry;
    int tid = threadIdx.x;
    int lane = tid & 31;
    int wid = tid >> 5;
    if (tid == 0) s_carry = 0;
    __syncthreads();

    for (int base = 0; base < n; base += 1024) {
        int i = base + tid;
        int v = (i < n) ? deg[i] : 0;
        int s = v;
        #pragma unroll
        for (int d = 1; d < 32; d <<= 1) {
            int t = __shfl_up_sync(0xffffffffu, s, d);
            if (lane >= d) s += t;
        }
        if (lane == 31) s_warp[wid] = s;
        __syncthreads();
        if (wid == 0) {
            int w = s_warp[lane];
            #pragma unroll
            for (int d = 1; d < 32; d <<= 1) {
                int t = __shfl_up_sync(0xffffffffu, w, d);
                if (lane >= d) w += t;
            }
            s_warp[lane] = w;
        }
        __syncthreads();
        int carry = s_carry;
        int excl = carry + (wid ? s_warp[wid - 1] : 0) + s - v;
        if (i < n) {
            rowstart[i] = excl;
            cursor[i]   = excl;
            invdeg[i]   = 1.0f / fmaxf((float)v, 1.0f);
        }
        __syncthreads();
        if (tid == 0) s_carry = carry + s_warp[31];
        __syncthreads();
    }
    if (tid == 0) rowstart[n] = s_carry;
}

// ---------------- CSR fill (both graphs) ----------------
__global__ void k_fill(const int* __restrict__ s0, const int* __restrict__ d0,
                       const int* __restrict__ s1, const int* __restrict__ d1,
                       int e0, int e1) {
    int gi = blockIdx.y;
    const int* __restrict__ src = gi ? s1 : s0;
    const int* __restrict__ dst = gi ? d1 : d0;
    int e = gi ? e1 : e0;
    int i = blockIdx.x * blockDim.x + threadIdx.x;
    if (i < e) {
        int p = atomicAdd(&g_cursor[gi][dst[i]], 1);
        g_csr[gi][p] = src[i];
    }
}

// ---------------- fused aggregate (mean over in-edges) + GEMM + bias ----------------
// block = 128 threads (one per feature), T=8 nodes, ONE graph per launch (L2 locality)
__global__ void __launch_bounds__(128, 8) k_layer(
    const float* __restrict__ feat, int gi, int sel_in, int sel_out,
    const float* __restrict__ W, const float* __restrict__ bias, int n)
{
    const float* __restrict__ h_in  = (sel_in < 0) ? feat : g_buf[gi][sel_in];
    float* __restrict__       h_out = g_buf[gi][sel_out];
    const int* __restrict__ rowstart = g_rowstart[gi];
    const int* __restrict__ csr = g_csr[gi];
    const float* __restrict__ invdeg = g_invdeg[gi];

    __shared__ float rows[D][RP];   // [k][t], stride 10 floats (8B aligned)
    int tid  = threadIdx.x;
    int base = blockIdx.x * T;

    // aggregation: thread tid accumulates feature column tid for each of T nodes
    #pragma unroll
    for (int t = 0; t < T; t++) {
        int node = base + t;
        float acc = 0.f;
        if (node < n) {
            int s = rowstart[node];
            int e = rowstart[node + 1];
            float a0 = 0.f, a1 = 0.f, a2 = 0.f, a3 = 0.f;
            float a4 = 0.f, a5 = 0.f, a6 = 0.f, a7 = 0.f;
            int i = s;
            for (; i + 8 <= e; i += 8) {
                int c0 = csr[i],     c1 = csr[i + 1], c2 = csr[i + 2], c3 = csr[i + 3];
                int c4 = csr[i + 4], c5 = csr[i + 5], c6 = csr[i + 6], c7 = csr[i + 7];
                a0 += __ldcg(&h_in[(size_t)c0 * D + tid]);
                a1 += __ldcg(&h_in[(size_t)c1 * D + tid]);
                a2 += __ldcg(&h_in[(size_t)c2 * D + tid]);
                a3 += __ldcg(&h_in[(size_t)c3 * D + tid]);
                a4 += __ldcg(&h_in[(size_t)c4 * D + tid]);
                a5 += __ldcg(&h_in[(size_t)c5 * D + tid]);
                a6 += __ldcg(&h_in[(size_t)c6 * D + tid]);
                a7 += __ldcg(&h_in[(size_t)c7 * D + tid]);
            }
            for (; i < e; i++) a0 += __ldcg(&h_in[(size_t)csr[i] * D + tid]);
            acc = (((a0 + a1) + (a2 + a3)) + ((a4 + a5) + (a6 + a7))) * invdeg[node];
        }
        rows[tid][t] = acc;
    }
    __syncthreads();

    // GEMM: out[node][tid] = sum_k rows[k][node] * W[k][tid] + b[tid]
    // packed f32x2 FMA: 4 accumulators of 2 floats each
    float bv = bias[tid];
    unsigned long long acc01 = pack2(bv, bv);
    unsigned long long acc23 = acc01, acc45 = acc01, acc67 = acc01;

    #pragma unroll 4
    for (int k = 0; k < D; k++) {
        float w = W[k * D + tid];
        unsigned long long w2 = pack2(w, w);
        const unsigned long long* rp = (const unsigned long long*)&rows[k][0];
        acc01 = fma2(rp[0], w2, acc01);
        acc23 = fma2(rp[1], w2, acc23);
        acc45 = fma2(rp[2], w2, acc45);
        acc67 = fma2(rp[3], w2, acc67);
    }

    float o[T];
    unpack2(acc01, o[0], o[1]);
    unpack2(acc23, o[2], o[3]);
    unpack2(acc45, o[4], o[5]);
    unpack2(acc67, o[6], o[7]);

    #pragma unroll
    for (int t = 0; t < T; t++) {
        int node = base + t;
        if (node < n) h_out[(size_t)node * D + tid] = o[t];
    }
}

// ---------------- readout column sums over final h (both graphs) ----------------
__global__ void k_colsum(int n) {
    int gi = blockIdx.y;
    float acc = 0.f;
    for (int node = blockIdx.x; node < n; node += gridDim.x)
        acc += g_buf[gi][0][(size_t)node * D + threadIdx.x];
    atomicAdd(&g_colsum[gi * D + threadIdx.x], acc);
}

// ---------------- final: readout MLP + match MLP + sigmoid ----------------
__global__ void k_match(const float* __restrict__ Wr,  const float* __restrict__ br,
                        const float* __restrict__ Wm1, const float* __restrict__ bm1,
                        const float* __restrict__ Wm2, const float* __restrict__ bm2,
                        float n_nodes, float* __restrict__ out)
{
    __shared__ float c[2 * D];
    __shared__ float red[D];
    int tid = threadIdx.x;          // 256 threads
    int g = tid / D;
    int j = tid % D;
    float invn = 1.0f / n_nodes;

    float acc = br[j];
    for (int k = 0; k < D; k++)
        acc += (g_colsum[g * D + k] * invn) * Wr[k * D + j];
    c[tid] = 1.0f / (1.0f + expf(-acc));    // g_p / g_s concatenated
    __syncthreads();

    if (tid < D) {
        float d1 = bm1[tid];
        for (int i = 0; i < 2 * D; i++)
            d1 += c[i] * Wm1[i * D + tid];
        red[tid] = d1 * Wm2[tid];
    }
    __syncthreads();

    if (tid == 0) {
        float s = 0.f;
        for (int i = 0; i < D; i++) s += red[i];
        out[0] = 1.0f / (1.0f + expf(-(s + bm2[0])));
    }
}

// ---------------- launch ----------------
extern "C" void kernel_launch(void* const* d_in, const int* in_sizes, int n_in,
                              void* d_out, int out_size)
{
    const float* feat_p = (const float*)d_in[0];
    const int*   src_p  = (const int*)d_in[1];
    const int*   dst_p  = (const int*)d_in[2];
    const float* feat_s = (const float*)d_in[3];
    const int*   src_s  = (const int*)d_in[4];
    const int*   dst_s  = (const int*)d_in[5];
    const float* W[3]   = { (const float*)d_in[6], (const float*)d_in[8], (const float*)d_in[10] };
    const float* b[3]   = { (const float*)d_in[7], (const float*)d_in[9], (const float*)d_in[11] };
    const float* Wr  = (const float*)d_in[12];
    const float* br  = (const float*)d_in[13];
    const float* Wm1 = (const float*)d_in[14];
    const float* bm1 = (const float*)d_in[15];
    const float* Wm2 = (const float*)d_in[16];
    const float* bm2 = (const float*)d_in[17];

    int n  = in_sizes[0] / D;
    int e0 = in_sizes[1];
    int e1 = in_sizes[4];
    int emax = e0 > e1 ? e0 : e1;

    dim3 gN((n + 511) / 512, 2);
    dim3 gE((emax + 511) / 512, 2);

    k_init<<<gN, 512>>>(n);
    k_count<<<gE, 512>>>(dst_p, dst_s, e0, e1);
    k_scan<<<2, 1024>>>(n);
    k_fill<<<gE, 512>>>(src_p, dst_p, src_s, dst_s, e0, e1);

    int nb = (n + T - 1) / T;
    // graphs sequential: keeps per-launch working set (~58 MB) L2-resident
    k_layer<<<nb, 128>>>(feat_p, 0, -1, 0, W[0], b[0], n);
    k_layer<<<nb, 128>>>(feat_p, 0,  0, 1, W[1], b[1], n);
    k_layer<<<nb, 128>>>(feat_p, 0,  1, 0, W[2], b[2], n);
    k_layer<<<nb, 128>>>(feat_s, 1, -1, 0, W[0], b[0], n);
    k_layer<<<nb, 128>>>(feat_s, 1,  0, 1, W[1], b[1], n);
    k_layer<<<nb, 128>>>(feat_s, 1,  1, 0, W[2], b[2], n);

    dim3 gC(512, 2);
    k_colsum<<<gC, 128>>>(n);

    k_match<<<1, 256>>>(Wr, br, Wm1, bm1, Wm2, bm2, (float)n, (float*)d_out);
}